// round 14
// baseline (speedup 1.0000x reference)
#include <cuda_runtime.h>
#include <cstdint>

#define NMAX 50000
#define EMAX 650000
#define H 128
#define KTOT 256
#define TPB 512
#define WROW 264   // k-pair row stride: 256 + 8 pad

// -------------------- scratch (no allocations allowed) ----------------------
__device__ float g_h0[NMAX * H];
__device__ float g_h1[NMAX * H];
__device__ float g_agg[NMAX * H];
__device__ float g_tmp1[NMAX * H];
__device__ float g_tmp2[NMAX * H];
__device__ int   g_cnt[NMAX];
__device__ int   g_off[NMAX];
__device__ int   g_cur[NMAX];
__device__ int   g_adj[EMAX];
__device__ int   g_blk[256];
// W images: [0]=W_in(K=256, 128 pair-rows), [1..4]=Wl1,Wr1,Wl2,Wr2 (K=128, 64 pair-rows)
__device__ __align__(16) float g_Wt[5][128 * WROW];

// -------------------- helpers ------------------------------------------------
__device__ __forceinline__ uint32_t tf32r(float x) {
    uint32_t r; asm("cvt.rna.tf32.f32 %0, %1;" : "=r"(r) : "f"(x));
    return r;
}
__device__ __forceinline__ void mma_tf32(float* d, const uint32_t* a, const uint32_t* b) {
    asm volatile("mma.sync.aligned.m16n8k8.row.col.f32.tf32.tf32.f32 "
                 "{%0,%1,%2,%3}, {%4,%5,%6,%7}, {%8,%9}, {%0,%1,%2,%3};"
                 : "+f"(d[0]), "+f"(d[1]), "+f"(d[2]), "+f"(d[3])
                 : "r"(a[0]), "r"(a[1]), "r"(a[2]), "r"(a[3]),
                   "r"(b[0]), "r"(b[1]));
}
__device__ __forceinline__ void cp16(uint32_t dst, const float* src) {
    asm volatile("cp.async.cg.shared.global [%0], [%1], 16;" :: "r"(dst), "l"(src));
}
__device__ __forceinline__ void cp_commit() {
    asm volatile("cp.async.commit_group;" ::: "memory");
}
template<int N>
__device__ __forceinline__ void cp_wait() {
    asm volatile("cp.async.wait_group %0;" :: "n"(N) : "memory");
}

// -------------------- weight prep: tf32-round into smem-image layouts --------
__global__ void prep_w(const float* __restrict__ W_in,
                       const float* __restrict__ Wl1, const float* __restrict__ Wr1,
                       const float* __restrict__ Wl2, const float* __restrict__ Wr2) {
    int i = blockIdx.x * blockDim.x + threadIdx.x;
    if (i >= KTOT * H + 4 * H * H) return;
    int m, k, col;
    float v;
    if (i < KTOT * H) {                 // W_in, K=256
        m = 0; k = i >> 7; col = i & 127;
        v = W_in[k * H + col];
    } else {
        int j = i - KTOT * H;
        m = 1 + (j >> 14);
        k = (j >> 7) & 127; col = j & 127;
        const float* src = (m == 1) ? Wl1 : (m == 2) ? Wr1 : (m == 3) ? Wl2 : Wr2;
        v = src[k * H + col];
    }
    int c  = k >> 5, kk = k & 31;
    int pr = ((kk >> 3) << 2) | (kk & 3);
    int s  = (kk >> 2) & 1;
    g_Wt[m][(c * 16 + pr) * WROW + col * 2 + s] = __uint_as_float(tf32r(v));
}

// -------------------- CSR build ----------------------------------------------
__global__ void zero_cnt(int n) {
    int i = blockIdx.x * blockDim.x + threadIdx.x;
    if (i < n) g_cnt[i] = 0;
}
__global__ void hist_kernel(const int* __restrict__ ei, int E) {
    int e = blockIdx.x * blockDim.x + threadIdx.x;
    if (e < E) atomicAdd(&g_cnt[__ldg(ei + E + e)], 1);
}
__global__ void scan1(int n) {
    __shared__ int smv[256];
    int t = threadIdx.x;
    int i = blockIdx.x * 256 + t;
    int v = (i < n) ? g_cnt[i] : 0;
    smv[t] = v;
    __syncthreads();
    #pragma unroll
    for (int off = 1; off < 256; off <<= 1) {
        int x = (t >= off) ? smv[t - off] : 0;
        __syncthreads();
        smv[t] += x;
        __syncthreads();
    }
    if (i < n) g_off[i] = smv[t] - v;
    if (t == 255) g_blk[blockIdx.x] = smv[255];
}
__global__ void scan2(int nb) {
    __shared__ int smv[256];
    int t = threadIdx.x;
    int v = (t < nb) ? g_blk[t] : 0;
    smv[t] = v;
    __syncthreads();
    #pragma unroll
    for (int off = 1; off < 256; off <<= 1) {
        int x = (t >= off) ? smv[t - off] : 0;
        __syncthreads();
        smv[t] += x;
        __syncthreads();
    }
    if (t < nb) g_blk[t] = smv[t] - v;
}
__global__ void scan3(int n) {
    int i = blockIdx.x * blockDim.x + threadIdx.x;
    if (i < n) {
        int o = g_off[i] + g_blk[i >> 8];
        g_off[i] = o;
        g_cur[i] = o;
    }
}
__global__ void fill_kernel(const int* __restrict__ ei, int E) {
    int e = blockIdx.x * blockDim.x + threadIdx.x;
    if (e < E) {
        int s = __ldg(ei + e);
        int d = __ldg(ei + E + e);
        int p = atomicAdd(&g_cur[d], 1);
        g_adj[p] = s;
    }
}

// -------------------- CSR aggregate: mean of h[src] per dst ------------------
template<int SRC>
__global__ void aggregate_kernel(int n) {
    int gw = (blockIdx.x * blockDim.x + threadIdx.x) >> 5;
    if (gw >= n) return;
    int lane = threadIdx.x & 31;
    const float* h = (SRC == 0) ? g_h0 : g_h1;
    int start = g_off[gw];
    int c = g_cnt[gw];
    float4 acc0 = make_float4(0.f, 0.f, 0.f, 0.f);
    float4 acc1 = make_float4(0.f, 0.f, 0.f, 0.f);
    int j = 0;
    for (; j + 2 <= c; j += 2) {
        int s0 = __ldg(g_adj + start + j);
        int s1 = __ldg(g_adj + start + j + 1);
        float4 v0 = __ldg((const float4*)(h + (size_t)s0 * H) + lane);
        float4 v1 = __ldg((const float4*)(h + (size_t)s1 * H) + lane);
        acc0.x += v0.x; acc0.y += v0.y; acc0.z += v0.z; acc0.w += v0.w;
        acc1.x += v1.x; acc1.y += v1.y; acc1.z += v1.z; acc1.w += v1.w;
    }
    if (j < c) {
        int s0 = __ldg(g_adj + start + j);
        float4 v0 = __ldg((const float4*)(h + (size_t)s0 * H) + lane);
        acc0.x += v0.x; acc0.y += v0.y; acc0.z += v0.z; acc0.w += v0.w;
    }
    float sc = (c > 0) ? (1.0f / (float)c) : 0.0f;
    float4 o;
    o.x = (acc0.x + acc1.x) * sc;
    o.y = (acc0.y + acc1.y) * sc;
    o.z = (acc0.z + acc1.z) * sc;
    o.w = (acc0.w + acc1.w) * sc;
    ((float4*)(g_agg + (size_t)gw * H))[lane] = o;
}

// smem layout (floats) — identical to R11
#define SMF_W     0                       // 3 * 16*264 = 12672 (W ring)
#define SMF_A     12672                   // 2 * 128*32 = 8192
#define SMF_C     20864                   // 768
#define SMF_RS    21632                   // 512
#define SMF_RSS   22144                   // 512
#define SMF_MU    22656                   // 128
#define SMF_RSTD  22784                   // 128
#define SMF_KIND  22912                   // 128
#define SMF_TOTAL 23040
#define SM_BYTES  (SMF_TOTAL * 4)

// -------- pipelined tf32 mma GEMM (R11 core), generalized --------------------
// KC = number of 32-k chunks (8 for K=256, 4 for K=128)
// EPI: 0 = +bias +kind_embed +relay*ext -> dst
//      1 = +bias                        -> dst (tmp)
//      2 = +tmpIn, LayerNorm, relu      -> dst
//      3 = +tmpIn                       -> dst
template<int KC, int EPI>
__global__ void __launch_bounds__(TPB, 1)
tc_gemm(const float* __restrict__ Asrc, int astride,
        const float* __restrict__ Wimg,
        const float* __restrict__ bias,
        const float* __restrict__ aux0,   // EPI0 kind_embed / EPI2 gamma
        const float* __restrict__ aux1,   // EPI0 ext_seed   / EPI2 beta
        const int*   __restrict__ node_kind,
        const float* __restrict__ tmpIn,
        float* __restrict__ dst,
        int n)
{
    extern __shared__ float sm[];
    float* Wring[3] = { sm + SMF_W, sm + SMF_W + 16 * WROW, sm + SMF_W + 32 * WROW };
    float* Abuf[2]  = { sm + SMF_A, sm + SMF_A + 128 * 32 };
    float* csh   = sm + SMF_C;
    float* rs    = sm + SMF_RS;
    float* rss   = sm + SMF_RSS;
    float* mus   = sm + SMF_MU;
    float* rstds = sm + SMF_RSTD;
    int*   kindsh = (int*)(sm + SMF_KIND);

    const int tid = threadIdx.x;
    const int wid = tid >> 5;
    const int lid = tid & 31;
    const int lq = lid >> 2;
    const int lr = lid & 3;
    const int wr = wid & 3;        // 4 row-blocks of 32
    const int cw = wid >> 2;       // 4 col-blocks of 32
    const int row0 = blockIdx.x << 7;

    const int arow = tid >> 2;     // 0..127
    const int ag   = tid & 3;      // k-group of 8
    const int agr  = row0 + arow;

    uint32_t wsh[3] = { (uint32_t)__cvta_generic_to_shared(Wring[0]),
                        (uint32_t)__cvta_generic_to_shared(Wring[1]),
                        (uint32_t)__cvta_generic_to_shared(Wring[2]) };

    float4 va, vb;
    auto ldgA = [&](int ch) {
        va = make_float4(0.f,0.f,0.f,0.f); vb = va;
        if (agr < n) {
            const float4* s = (const float4*)(Asrc + (size_t)agr * astride + ch * 32 + ag * 8);
            va = __ldg(s); vb = __ldg(s + 1);
        }
    };
    auto stsA = [&](int p) {
        uint4 s0, s1;
        s0.x = tf32r(va.x); s0.y = tf32r(vb.x);
        s0.z = tf32r(va.y); s0.w = tf32r(vb.y);
        s1.x = tf32r(va.z); s1.y = tf32r(vb.z);
        s1.z = tf32r(va.w); s1.w = tf32r(vb.w);
        int u0 = (ag * 2) ^ ((arow & 3) << 1);
        uint4* d = (uint4*)&Abuf[p][arow * 32 + u0 * 4];
        d[0] = s0; d[1] = s1;
    };
    auto copyW = [&](int ch, int p) {
        const float* src = Wimg + ch * 16 * WROW;
        #pragma unroll
        for (int j = 0; j < 3; j++) {
            int f4 = tid + j * TPB;
            if (f4 < 1056) {
                int off = f4 * 4;
                cp16(wsh[p] + off * 4, src + off);
            }
        }
    };

    // ---- prologue ----
    copyW(0, 0); cp_commit();
    copyW(1, 1); cp_commit();
    ldgA(0);
    if (EPI <= 1) { if (tid < H) csh[tid] = __ldg(bias + tid); }
    if (EPI == 0) {
        if (tid >= H && tid < H + 3 * H) csh[tid] = __ldg(aux0 + (tid - H));
        if (tid < H) csh[4 * H + tid] = __ldg(aux1 + tid);
        if (tid < 128) kindsh[tid] = (row0 + tid < n) ? __ldg(node_kind + row0 + tid) : 0;
    } else if (EPI == 2) {
        if (tid < H) { csh[H + tid] = __ldg(aux0 + tid); csh[2 * H + tid] = __ldg(aux1 + tid); }
    }
    stsA(0);
    ldgA(1);
    cp_wait<1>();
    __syncthreads();

    float acc[2][4][4];
    #pragma unroll
    for (int mf = 0; mf < 2; mf++)
        #pragma unroll
        for (int nf = 0; nf < 4; nf++)
            #pragma unroll
            for (int q = 0; q < 4; q++) acc[mf][nf][q] = 0.f;

    int p = 0;
    #pragma unroll
    for (int ch = 0; ch < KC; ch++) {
        if (ch + 2 < KC) { copyW(ch + 2, (ch + 2) % 3); cp_commit(); }

        const float* Ab = Abuf[p];
        const float* Wb = Wring[ch % 3];
        #pragma unroll
        for (int ks = 0; ks < 4; ks++) {
            uint32_t a[2][4];
            #pragma unroll
            for (int mf = 0; mf < 2; mf++) {
                int rlo = wr * 32 + mf * 16 + lq;
                int u = (ks * 2 + (lr >> 1)) ^ ((lq & 3) << 1);
                float2 lo = *(const float2*)&Ab[rlo * 32 + u * 4 + (lr & 1) * 2];
                float2 hi = *(const float2*)&Ab[(rlo + 8) * 32 + u * 4 + (lr & 1) * 2];
                a[mf][0] = __float_as_uint(lo.x);
                a[mf][1] = __float_as_uint(hi.x);
                a[mf][2] = __float_as_uint(lo.y);
                a[mf][3] = __float_as_uint(hi.y);
            }
            uint32_t b[4][2];
            #pragma unroll
            for (int nf = 0; nf < 4; nf++) {
                float2 bv = *(const float2*)&Wb[(ks * 4 + lr) * WROW
                                                + (cw * 32 + nf * 8 + lq) * 2];
                b[nf][0] = __float_as_uint(bv.x);
                b[nf][1] = __float_as_uint(bv.y);
            }
            #pragma unroll
            for (int mf = 0; mf < 2; mf++)
                #pragma unroll
                for (int nf = 0; nf < 4; nf++)
                    mma_tf32(acc[mf][nf], a[mf], b[nf]);
        }
        if (ch < KC - 1) {
            stsA(p ^ 1);
            if (ch < KC - 2) ldgA(ch + 2);
            if (ch + 2 < KC) cp_wait<1>(); else cp_wait<0>();
        }
        __syncthreads();
        p ^= 1;
    }

    // ---------------- epilogue ----------------
    if (EPI <= 1) {
        #pragma unroll
        for (int mf = 0; mf < 2; mf++)
            #pragma unroll
            for (int nf = 0; nf < 4; nf++) {
                int c0 = cw * 32 + nf * 8 + 2 * lr;
                float b0v = csh[c0], b1v = csh[c0 + 1];
                acc[mf][nf][0] += b0v; acc[mf][nf][1] += b1v;
                acc[mf][nf][2] += b0v; acc[mf][nf][3] += b1v;
            }
    } else {
        // add tmpIn
        #pragma unroll
        for (int mf = 0; mf < 2; mf++) {
            int lrow = wr * 32 + mf * 16 + lq;
            int glo = row0 + lrow, ghi = glo + 8;
            #pragma unroll
            for (int nf = 0; nf < 4; nf++) {
                int c0 = cw * 32 + nf * 8 + 2 * lr;
                if (glo < n) {
                    float2 t = *(const float2*)(tmpIn + (size_t)glo * H + c0);
                    acc[mf][nf][0] += t.x; acc[mf][nf][1] += t.y;
                }
                if (ghi < n) {
                    float2 t = *(const float2*)(tmpIn + (size_t)ghi * H + c0);
                    acc[mf][nf][2] += t.x; acc[mf][nf][3] += t.y;
                }
            }
        }
    }

    if (EPI == 2) {
        #pragma unroll
        for (int mf = 0; mf < 2; mf++) {
            float slo = 0.f, sslo = 0.f, shi = 0.f, sshi = 0.f;
            #pragma unroll
            for (int nf = 0; nf < 4; nf++) {
                float v0 = acc[mf][nf][0], v1 = acc[mf][nf][1];
                float v2 = acc[mf][nf][2], v3 = acc[mf][nf][3];
                slo += v0 + v1;  sslo += v0 * v0 + v1 * v1;
                shi += v2 + v3;  sshi += v2 * v2 + v3 * v3;
            }
            #pragma unroll
            for (int m = 1; m <= 2; m <<= 1) {
                slo  += __shfl_xor_sync(0xffffffffu, slo,  m);
                sslo += __shfl_xor_sync(0xffffffffu, sslo, m);
                shi  += __shfl_xor_sync(0xffffffffu, shi,  m);
                sshi += __shfl_xor_sync(0xffffffffu, sshi, m);
            }
            if (lr == 0) {
                int rlo = wr * 32 + mf * 16 + lq;
                rs [rlo * 4 + cw] = slo;       rss[rlo * 4 + cw] = sslo;
                rs [(rlo + 8) * 4 + cw] = shi; rss[(rlo + 8) * 4 + cw] = sshi;
            }
        }
        __syncthreads();
        if (tid < 128) {
            float s  = rs [tid * 4] + rs [tid * 4 + 1] + rs [tid * 4 + 2] + rs [tid * 4 + 3];
            float ss = rss[tid * 4] + rss[tid * 4 + 1] + rss[tid * 4 + 2] + rss[tid * 4 + 3];
            float mu  = s * (1.0f / H);
            float var = ss * (1.0f / H) - mu * mu;
            mus[tid] = mu;
            rstds[tid] = rsqrtf(var + 1e-5f);
        }
        __syncthreads();
        #pragma unroll
        for (int mf = 0; mf < 2; mf++) {
            int lrow = wr * 32 + mf * 16 + lq;
            float mu_lo = mus[lrow],     rd_lo = rstds[lrow];
            float mu_hi = mus[lrow + 8], rd_hi = rstds[lrow + 8];
            int glo = row0 + lrow, ghi = glo + 8;
            #pragma unroll
            for (int nf = 0; nf < 4; nf++) {
                int c0 = cw * 32 + nf * 8 + 2 * lr;
                float g0 = csh[H + c0], g1 = csh[H + c0 + 1];
                float be0 = csh[2 * H + c0], be1 = csh[2 * H + c0 + 1];
                if (glo < n) {
                    float2 o;
                    o.x = fmaxf((acc[mf][nf][0] - mu_lo) * rd_lo * g0 + be0, 0.f);
                    o.y = fmaxf((acc[mf][nf][1] - mu_lo) * rd_lo * g1 + be1, 0.f);
                    *(float2*)(dst + (size_t)glo * H + c0) = o;
                }
                if (ghi < n) {
                    float2 o;
                    o.x = fmaxf((acc[mf][nf][2] - mu_hi) * rd_hi * g0 + be0, 0.f);
                    o.y = fmaxf((acc[mf][nf][3] - mu_hi) * rd_hi * g1 + be1, 0.f);
                    *(float2*)(dst + (size_t)ghi * H + c0) = o;
                }
            }
        }
    } else {
        #pragma unroll
        for (int mf = 0; mf < 2; mf++) {
            int lrow = wr * 32 + mf * 16 + lq;
            int glo = row0 + lrow, ghi = glo + 8;
            int klo = 0, khi = 0;
            bool rlo = false, rhi = false;
            if (EPI == 0) {
                klo = kindsh[lrow]; khi = kindsh[lrow + 8];
                rlo = (klo != 0);   rhi = (khi != 0);
            }
            #pragma unroll
            for (int nf = 0; nf < 4; nf++) {
                int c0 = cw * 32 + nf * 8 + 2 * lr;
                if (glo < n) {
                    float2 o = make_float2(acc[mf][nf][0], acc[mf][nf][1]);
                    if (EPI == 0) {
                        o.x += csh[H + klo * H + c0];
                        o.y += csh[H + klo * H + c0 + 1];
                        if (rlo) { o.x += csh[4 * H + c0]; o.y += csh[4 * H + c0 + 1]; }
                    }
                    *(float2*)(dst + (size_t)glo * H + c0) = o;
                }
                if (ghi < n) {
                    float2 o = make_float2(acc[mf][nf][2], acc[mf][nf][3]);
                    if (EPI == 0) {
                        o.x += csh[H + khi * H + c0];
                        o.y += csh[H + khi * H + c0 + 1];
                        if (rhi) { o.x += csh[4 * H + c0]; o.y += csh[4 * H + c0 + 1]; }
                    }
                    *(float2*)(dst + (size_t)ghi * H + c0) = o;
                }
            }
        }
    }
}

// ---------------------------------------------------------------------------
extern "C" void kernel_launch(void* const* d_in, const int* in_sizes, int n_in,
                              void* d_out, int out_size) {
    const float* x          = (const float*)d_in[0];
    const int*   ei         = (const int*)d_in[1];
    const int*   node_kind  = (const int*)d_in[2];
    const float* W_in       = (const float*)d_in[3];
    const float* b_in       = (const float*)d_in[4];
    const float* kind_embed = (const float*)d_in[5];
    const float* ext_seed   = (const float*)d_in[6];
    const float* Wl1        = (const float*)d_in[7];
    const float* bl1        = (const float*)d_in[8];
    const float* Wr1        = (const float*)d_in[9];
    const float* gamma      = (const float*)d_in[10];
    const float* beta       = (const float*)d_in[11];
    const float* Wl2        = (const float*)d_in[12];
    const float* bl2        = (const float*)d_in[13];
    const float* Wr2        = (const float*)d_in[14];

    int n = in_sizes[2];
    int E = in_sizes[1] / 2;

    cudaFuncSetAttribute(tc_gemm<8,0>, cudaFuncAttributeMaxDynamicSharedMemorySize, SM_BYTES);
    cudaFuncSetAttribute(tc_gemm<4,1>, cudaFuncAttributeMaxDynamicSharedMemorySize, SM_BYTES);
    cudaFuncSetAttribute(tc_gemm<4,2>, cudaFuncAttributeMaxDynamicSharedMemorySize, SM_BYTES);
    cudaFuncSetAttribute(tc_gemm<4,3>, cudaFuncAttributeMaxDynamicSharedMemorySize, SM_BYTES);

    int ntiles = (n + 127) / 128;
    int nb256  = (n + 255) / 256;
    int eb256  = (E + 255) / 256;
    int aggblk = (n * 32 + 255) / 256;

    // device-global W images / hidden buffers (symbol addresses)
    float *wt0, *wt1, *wt2, *wt3, *wt4, *h0, *h1, *agg, *tmp1, *tmp2;
    cudaGetSymbolAddress((void**)&wt0, g_Wt);
    wt1 = wt0 + 1 * 128 * WROW;
    wt2 = wt0 + 2 * 128 * WROW;
    wt3 = wt0 + 3 * 128 * WROW;
    wt4 = wt0 + 4 * 128 * WROW;
    cudaGetSymbolAddress((void**)&h0,  g_h0);
    cudaGetSymbolAddress((void**)&h1,  g_h1);
    cudaGetSymbolAddress((void**)&agg, g_agg);
    cudaGetSymbolAddress((void**)&tmp1, g_tmp1);
    cudaGetSymbolAddress((void**)&tmp2, g_tmp2);

    cudaStream_t s2;
    cudaStreamCreateWithFlags(&s2, cudaStreamNonBlocking);
    cudaEvent_t e1, eCSR, eH0, eR1, eH1, eR2;
    cudaEventCreateWithFlags(&e1,   cudaEventDisableTiming);
    cudaEventCreateWithFlags(&eCSR, cudaEventDisableTiming);
    cudaEventCreateWithFlags(&eH0,  cudaEventDisableTiming);
    cudaEventCreateWithFlags(&eR1,  cudaEventDisableTiming);
    cudaEventCreateWithFlags(&eH1,  cudaEventDisableTiming);
    cudaEventCreateWithFlags(&eR2,  cudaEventDisableTiming);

    // ---- fork: CSR build on side stream ----
    cudaEventRecord(e1, 0);
    cudaStreamWaitEvent(s2, e1, 0);
    zero_cnt<<<nb256, 256, 0, s2>>>(n);
    hist_kernel<<<eb256, 256, 0, s2>>>(ei, E);
    scan1<<<nb256, 256, 0, s2>>>(n);
    scan2<<<1, 256, 0, s2>>>(nb256);
    scan3<<<nb256, 256, 0, s2>>>(n);
    fill_kernel<<<eb256, 256, 0, s2>>>(ei, E);
    cudaEventRecord(eCSR, s2);

    // main: prep_w + gemm0 -> h0 (overlaps CSR)
    prep_w<<<(KTOT * H + 4 * H * H + 255) / 256, 256>>>(W_in, Wl1, Wr1, Wl2, Wr2);
    tc_gemm<8,0><<<ntiles, TPB, SM_BYTES>>>(x, KTOT, wt0, b_in, kind_embed,
                                            ext_seed, node_kind, nullptr, h0, n);
    cudaEventRecord(eH0, 0);

    // s2: R1 = h0 @ Wr1 + bl1 -> tmp1  (concurrent with aggregate<0>)
    cudaStreamWaitEvent(s2, eH0, 0);
    tc_gemm<4,1><<<ntiles, TPB, SM_BYTES, s2>>>(h0, H, wt2, bl1, nullptr,
                                                nullptr, nullptr, nullptr, tmp1, n);
    cudaEventRecord(eR1, s2);

    // main: aggregate<0> (needs CSR + h0)
    cudaStreamWaitEvent(0, eCSR, 0);
    aggregate_kernel<0><<<aggblk, 256>>>(n);

    // main: L1 = agg @ Wl1 + tmp1, LN, relu -> h1
    cudaStreamWaitEvent(0, eR1, 0);
    tc_gemm<4,2><<<ntiles, TPB, SM_BYTES>>>(agg, H, wt1, nullptr, gamma,
                                            beta, nullptr, tmp1, h1, n);
    cudaEventRecord(eH1, 0);

    // s2: R2 = h1 @ Wr2 + bl2 -> tmp2 (concurrent with aggregate<1>)
    cudaStreamWaitEvent(s2, eH1, 0);
    tc_gemm<4,1><<<ntiles, TPB, SM_BYTES, s2>>>(h1, H, wt4, bl2, nullptr,
                                                nullptr, nullptr, nullptr, tmp2, n);
    cudaEventRecord(eR2, s2);

    // main: aggregate<1> (h1)
    aggregate_kernel<1><<<aggblk, 256>>>(n);

    // main: L2 = agg @ Wl2 + tmp2 -> out
    cudaStreamWaitEvent(0, eR2, 0);
    tc_gemm<4,3><<<ntiles, TPB, SM_BYTES>>>(agg, H, wt3, nullptr, nullptr,
                                            nullptr, nullptr, tmp2, (float*)d_out, n);
}

// round 15
// speedup vs baseline: 1.0674x; 1.0674x over previous
#include <cuda_runtime.h>
#include <cstdint>

#define NMAX 50000
#define EMAX 650000
#define H 128
#define KTOT 256
#define TPB 256
#define WROW 264   // k-pair row stride: 256 + 8 pad

// -------------------- scratch (no allocations allowed) ----------------------
__device__ float g_h0[NMAX * H];
__device__ float g_h1[NMAX * H];
__device__ float g_agg[NMAX * H];
__device__ int   g_cnt[NMAX];
__device__ int   g_off[NMAX];
__device__ int   g_cur[NMAX];
__device__ int   g_adj[EMAX];
__device__ int   g_blk[256];
__device__ __align__(16) float g_Wt[3][128 * WROW];  // tf32-rounded smem image

// -------------------- helpers ------------------------------------------------
__device__ __forceinline__ uint32_t tf32r(float x) {
    uint32_t r; asm("cvt.rna.tf32.f32 %0, %1;" : "=r"(r) : "f"(x));
    return r;
}
__device__ __forceinline__ void mma_tf32(float* d, const uint32_t* a, const uint32_t* b) {
    asm volatile("mma.sync.aligned.m16n8k8.row.col.f32.tf32.tf32.f32 "
                 "{%0,%1,%2,%3}, {%4,%5,%6,%7}, {%8,%9}, {%0,%1,%2,%3};"
                 : "+f"(d[0]), "+f"(d[1]), "+f"(d[2]), "+f"(d[3])
                 : "r"(a[0]), "r"(a[1]), "r"(a[2]), "r"(a[3]),
                   "r"(b[0]), "r"(b[1]));
}
__device__ __forceinline__ void cp16(uint32_t dst, const float* src) {
    asm volatile("cp.async.cg.shared.global [%0], [%1], 16;" :: "r"(dst), "l"(src));
}
__device__ __forceinline__ void cp_commit() {
    asm volatile("cp.async.commit_group;" ::: "memory");
}
template<int N>
__device__ __forceinline__ void cp_wait() {
    asm volatile("cp.async.wait_group %0;" :: "n"(N) : "memory");
}

// -------------------- weight prep: tf32-round into smem-image layout ---------
__global__ void prep_w(const float* __restrict__ W_in,
                       const float* __restrict__ Wl1, const float* __restrict__ Wr1,
                       const float* __restrict__ Wl2, const float* __restrict__ Wr2) {
    int i = blockIdx.x * blockDim.x + threadIdx.x;
    if (i >= 3 * KTOT * H) return;
    int col = i & 127;
    int k   = (i >> 7) & 255;
    int m   = i >> 15;
    float v;
    if (m == 0)      v = W_in[k * H + col];
    else if (m == 1) v = (k < H) ? Wl1[k * H + col] : Wr1[(k - H) * H + col];
    else             v = (k < H) ? Wl2[k * H + col] : Wr2[(k - H) * H + col];
    int c  = k >> 5, kk = k & 31;
    int pr = ((kk >> 3) << 2) | (kk & 3);
    int s  = (kk >> 2) & 1;
    g_Wt[m][(c * 16 + pr) * WROW + col * 2 + s] = __uint_as_float(tf32r(v));
}

// -------------------- CSR build ----------------------------------------------
__global__ void zero_cnt(int n) {
    int i = blockIdx.x * blockDim.x + threadIdx.x;
    if (i < n) g_cnt[i] = 0;
}
__global__ void hist_kernel(const int* __restrict__ ei, int E) {
    int e = blockIdx.x * blockDim.x + threadIdx.x;
    if (e < E) atomicAdd(&g_cnt[__ldg(ei + E + e)], 1);
}
__global__ void scan1(int n) {
    __shared__ int smv[256];
    int t = threadIdx.x;
    int i = blockIdx.x * 256 + t;
    int v = (i < n) ? g_cnt[i] : 0;
    smv[t] = v;
    __syncthreads();
    #pragma unroll
    for (int off = 1; off < 256; off <<= 1) {
        int x = (t >= off) ? smv[t - off] : 0;
        __syncthreads();
        smv[t] += x;
        __syncthreads();
    }
    if (i < n) g_off[i] = smv[t] - v;
    if (t == 255) g_blk[blockIdx.x] = smv[255];
}
__global__ void scan2(int nb) {
    __shared__ int smv[256];
    int t = threadIdx.x;
    int v = (t < nb) ? g_blk[t] : 0;
    smv[t] = v;
    __syncthreads();
    #pragma unroll
    for (int off = 1; off < 256; off <<= 1) {
        int x = (t >= off) ? smv[t - off] : 0;
        __syncthreads();
        smv[t] += x;
        __syncthreads();
    }
    if (t < nb) g_blk[t] = smv[t] - v;
}
__global__ void scan3(int n) {
    int i = blockIdx.x * blockDim.x + threadIdx.x;
    if (i < n) {
        int o = g_off[i] + g_blk[i >> 8];
        g_off[i] = o;
        g_cur[i] = o;
    }
}
__global__ void fill_kernel(const int* __restrict__ ei, int E) {
    int e = blockIdx.x * blockDim.x + threadIdx.x;
    if (e < E) {
        int s = __ldg(ei + e);
        int d = __ldg(ei + E + e);
        int p = atomicAdd(&g_cur[d], 1);
        g_adj[p] = s;
    }
}

// -------------------- CSR aggregate: mean of h[src] per dst ------------------
template<int SRC>
__global__ void aggregate_kernel(int n) {
    int gw = (blockIdx.x * blockDim.x + threadIdx.x) >> 5;
    if (gw >= n) return;
    int lane = threadIdx.x & 31;
    const float* h = (SRC == 0) ? g_h0 : g_h1;
    int start = g_off[gw];
    int c = g_cnt[gw];
    float4 acc0 = make_float4(0.f, 0.f, 0.f, 0.f);
    float4 acc1 = make_float4(0.f, 0.f, 0.f, 0.f);
    int j = 0;
    for (; j + 2 <= c; j += 2) {
        int s0 = __ldg(g_adj + start + j);
        int s1 = __ldg(g_adj + start + j + 1);
        float4 v0 = __ldg((const float4*)(h + (size_t)s0 * H) + lane);
        float4 v1 = __ldg((const float4*)(h + (size_t)s1 * H) + lane);
        acc0.x += v0.x; acc0.y += v0.y; acc0.z += v0.z; acc0.w += v0.w;
        acc1.x += v1.x; acc1.y += v1.y; acc1.z += v1.z; acc1.w += v1.w;
    }
    if (j < c) {
        int s0 = __ldg(g_adj + start + j);
        float4 v0 = __ldg((const float4*)(h + (size_t)s0 * H) + lane);
        acc0.x += v0.x; acc0.y += v0.y; acc0.z += v0.z; acc0.w += v0.w;
    }
    float sc = (c > 0) ? (1.0f / (float)c) : 0.0f;
    float4 o;
    o.x = (acc0.x + acc1.x) * sc;
    o.y = (acc0.y + acc1.y) * sc;
    o.z = (acc0.z + acc1.z) * sc;
    o.w = (acc0.w + acc1.w) * sc;
    ((float4*)(g_agg + (size_t)gw * H))[lane] = o;
}

// smem layout (floats) — same footprint as R11
#define SMF_W     0                       // 3 * 16*264 = 12672 (W ring)
#define SMF_A     12672                   // 2 * 128*32 = 8192
#define SMF_C     20864                   // 768
#define SMF_RS    21632                   // 512
#define SMF_RSS   22144                   // 512
#define SMF_MU    22656                   // 128
#define SMF_RSTD  22784                   // 128
#define SMF_KIND  22912                   // 128
#define SMF_TOTAL 23040
#define SM_BYTES  (SMF_TOTAL * 4)

// ---- pipelined tf32 mma GEMM: 8 warps (64x32 tiles), cp.async W ring, 2 CTA/SM
// MODE 0: A=x[N,256], W=Wt0 -> h0 = ..+b_in+kind_embed[k]+relay*ext
// MODE 1: A=[agg | h0], W=Wt1 -> relu(LN(..+bl1)) -> h1
// MODE 2: A=[agg | h1], W=Wt2 -> ..+bl2 -> out
template<int MODE>
__global__ void __launch_bounds__(TPB, 2)
tc_gemm(const float* __restrict__ Aext,
        const float* __restrict__ bias,
        const float* __restrict__ aux0,   // MODE0 kind_embed / MODE1 gamma
        const float* __restrict__ aux1,   // MODE0 ext_seed   / MODE1 beta
        const int*   __restrict__ node_kind,
        float* __restrict__ outExt,
        int n)
{
    extern __shared__ float sm[];
    float* Wring[3] = { sm + SMF_W, sm + SMF_W + 16 * WROW, sm + SMF_W + 32 * WROW };
    float* Abuf[2]  = { sm + SMF_A, sm + SMF_A + 128 * 32 };
    float* csh   = sm + SMF_C;
    float* rs    = sm + SMF_RS;
    float* rss   = sm + SMF_RSS;
    float* mus   = sm + SMF_MU;
    float* rstds = sm + SMF_RSTD;
    int*   kindsh = (int*)(sm + SMF_KIND);

    const int tid = threadIdx.x;
    const int wid = tid >> 5;
    const int lid = tid & 31;
    const int lq = lid >> 2;
    const int lr = lid & 3;
    const int wr = wid & 1;        // 2 row-blocks of 64
    const int cw = wid >> 1;       // 4 col-blocks of 32
    const int row0 = blockIdx.x << 7;

    // A staging roles: 2 threads per row, each 16 consecutive k floats
    const int arow  = tid >> 1;    // 0..127
    const int khalf = tid & 1;     // 0/1 -> k offset 0/16
    const int agr   = row0 + arow;

    const float* Asrc = (MODE == 1) ? (const float*)g_h0 : (const float*)g_h1;
    const float* Wt = g_Wt[MODE];

    uint32_t wsh[3] = { (uint32_t)__cvta_generic_to_shared(Wring[0]),
                        (uint32_t)__cvta_generic_to_shared(Wring[1]),
                        (uint32_t)__cvta_generic_to_shared(Wring[2]) };

    float4 va0, va1, va2, va3;

    auto ldgA = [&](int ch) {
        va0 = make_float4(0.f,0.f,0.f,0.f); va1 = va0; va2 = va0; va3 = va0;
        if (agr < n) {
            const float4* s;
            if (MODE == 0)   s = (const float4*)(Aext  + (size_t)agr * KTOT + ch * 32 + khalf * 16);
            else if (ch < 4) s = (const float4*)(g_agg + (size_t)agr * H + ch * 32 + khalf * 16);
            else             s = (const float4*)(Asrc  + (size_t)agr * H + (ch - 4) * 32 + khalf * 16);
            va0 = __ldg(s); va1 = __ldg(s + 1); va2 = __ldg(s + 2); va3 = __ldg(s + 3);
        }
    };
    auto stsA = [&](int p) {
        #pragma unroll
        for (int g = 0; g < 2; g++) {
            float4 xa = g ? va2 : va0;
            float4 xb = g ? va3 : va1;
            int ag = khalf * 2 + g;
            uint4 s0, s1;
            s0.x = tf32r(xa.x); s0.y = tf32r(xb.x);
            s0.z = tf32r(xa.y); s0.w = tf32r(xb.y);
            s1.x = tf32r(xa.z); s1.y = tf32r(xb.z);
            s1.z = tf32r(xa.w); s1.w = tf32r(xb.w);
            int u0 = (ag * 2) ^ ((arow & 3) << 1);
            uint4* d = (uint4*)&Abuf[p][arow * 32 + u0 * 4];
            d[0] = s0; d[1] = s1;
        }
    };
    auto copyW = [&](int ch, int p) {
        const float* src = Wt + ch * 16 * WROW;
        #pragma unroll
        for (int j = 0; j < 5; j++) {
            int f4 = tid + j * TPB;
            if (f4 < 1056) {
                int off = f4 * 4;
                cp16(wsh[p] + off * 4, src + off);
            }
        }
    };

    // ---- prologue: W chunks 0,1 in flight; consts; A chunk 0 staged ----
    copyW(0, 0); cp_commit();
    copyW(1, 1); cp_commit();
    ldgA(0);
    if (tid < H) csh[tid] = __ldg(bias + tid);
    if (MODE == 0) {
        for (int i = tid; i < 3 * H; i += TPB) csh[H + i] = __ldg(aux0 + i);
        if (tid < H) csh[4 * H + tid] = __ldg(aux1 + tid);
        if (tid < 128) kindsh[tid] = (row0 + tid < n) ? __ldg(node_kind + row0 + tid) : 0;
    } else if (MODE == 1) {
        if (tid < H) { csh[H + tid] = __ldg(aux0 + tid); csh[2 * H + tid] = __ldg(aux1 + tid); }
    }
    stsA(0);
    ldgA(1);
    cp_wait<1>();      // W chunk 0 landed
    __syncthreads();

    float acc[4][4][4];
    #pragma unroll
    for (int mf = 0; mf < 4; mf++)
        #pragma unroll
        for (int nf = 0; nf < 4; nf++)
            #pragma unroll
            for (int q = 0; q < 4; q++) acc[mf][nf][q] = 0.f;

    int p = 0;
    #pragma unroll
    for (int ch = 0; ch < 8; ch++) {
        // prefetch W chunk ch+2 into ring slot (ch+2)%3 — last read in chunk
        // ch-1, retired by the barrier that ended chunk ch-1 (R11 schedule).
        if (ch + 2 < 8) { copyW(ch + 2, (ch + 2) % 3); cp_commit(); }

        const float* Ab = Abuf[p];
        const float* Wb = Wring[ch % 3];
        #pragma unroll
        for (int ks = 0; ks < 4; ks++) {
            uint32_t a[4][4];
            #pragma unroll
            for (int mf = 0; mf < 4; mf++) {
                int rlo = wr * 64 + mf * 16 + lq;
                int u = (ks * 2 + (lr >> 1)) ^ ((lq & 3) << 1);
                float2 lo = *(const float2*)&Ab[rlo * 32 + u * 4 + (lr & 1) * 2];
                float2 hi = *(const float2*)&Ab[(rlo + 8) * 32 + u * 4 + (lr & 1) * 2];
                a[mf][0] = __float_as_uint(lo.x);
                a[mf][1] = __float_as_uint(hi.x);
                a[mf][2] = __float_as_uint(lo.y);
                a[mf][3] = __float_as_uint(hi.y);
            }
            uint32_t b[4][2];
            #pragma unroll
            for (int nf = 0; nf < 4; nf++) {
                float2 bv = *(const float2*)&Wb[(ks * 4 + lr) * WROW
                                                + (cw * 32 + nf * 8 + lq) * 2];
                b[nf][0] = __float_as_uint(bv.x);
                b[nf][1] = __float_as_uint(bv.y);
            }
            #pragma unroll
            for (int mf = 0; mf < 4; mf++)
                #pragma unroll
                for (int nf = 0; nf < 4; nf++)
                    mma_tf32(acc[mf][nf], a[mf], b[nf]);
        }
        if (ch < 7) {
            stsA(p ^ 1);                 // buffer p^1 retired at end of ch-1
            if (ch < 6) ldgA(ch + 2);
            if (ch + 2 < 8) cp_wait<1>(); else cp_wait<0>();  // chunk ch+1 landed
        }
        __syncthreads();
        p ^= 1;
    }

    // ---------------- epilogue (R9-validated 4-mf version) ----------------
    #pragma unroll
    for (int mf = 0; mf < 4; mf++)
        #pragma unroll
        for (int nf = 0; nf < 4; nf++) {
            int c0 = cw * 32 + nf * 8 + 2 * lr;
            float b0v = csh[c0], b1v = csh[c0 + 1];
            acc[mf][nf][0] += b0v; acc[mf][nf][1] += b1v;
            acc[mf][nf][2] += b0v; acc[mf][nf][3] += b1v;
        }

    if (MODE == 1) {
        #pragma unroll
        for (int mf = 0; mf < 4; mf++) {
            float slo = 0.f, sslo = 0.f, shi = 0.f, sshi = 0.f;
            #pragma unroll
            for (int nf = 0; nf < 4; nf++) {
                float v0 = acc[mf][nf][0], v1 = acc[mf][nf][1];
                float v2 = acc[mf][nf][2], v3 = acc[mf][nf][3];
                slo += v0 + v1;  sslo += v0 * v0 + v1 * v1;
                shi += v2 + v3;  sshi += v2 * v2 + v3 * v3;
            }
            #pragma unroll
            for (int m = 1; m <= 2; m <<= 1) {
                slo  += __shfl_xor_sync(0xffffffffu, slo,  m);
                sslo += __shfl_xor_sync(0xffffffffu, sslo, m);
                shi  += __shfl_xor_sync(0xffffffffu, shi,  m);
                sshi += __shfl_xor_sync(0xffffffffu, sshi, m);
            }
            if (lr == 0) {
                int rlo = wr * 64 + mf * 16 + lq;
                rs [rlo * 4 + cw] = slo;       rss[rlo * 4 + cw] = sslo;
                rs [(rlo + 8) * 4 + cw] = shi; rss[(rlo + 8) * 4 + cw] = sshi;
            }
        }
        __syncthreads();
        if (tid < 128) {
            float s  = rs [tid * 4] + rs [tid * 4 + 1] + rs [tid * 4 + 2] + rs [tid * 4 + 3];
            float ss = rss[tid * 4] + rss[tid * 4 + 1] + rss[tid * 4 + 2] + rss[tid * 4 + 3];
            float mu  = s * (1.0f / H);
            float var = ss * (1.0f / H) - mu * mu;
            mus[tid] = mu;
            rstds[tid] = rsqrtf(var + 1e-5f);
        }
        __syncthreads();
        #pragma unroll
        for (int mf = 0; mf < 4; mf++) {
            int lrow = wr * 64 + mf * 16 + lq;
            float mu_lo = mus[lrow],     rd_lo = rstds[lrow];
            float mu_hi = mus[lrow + 8], rd_hi = rstds[lrow + 8];
            int glo = row0 + lrow, ghi = glo + 8;
            #pragma unroll
            for (int nf = 0; nf < 4; nf++) {
                int c0 = cw * 32 + nf * 8 + 2 * lr;
                float g0 = csh[H + c0], g1 = csh[H + c0 + 1];
                float be0 = csh[2 * H + c0], be1 = csh[2 * H + c0 + 1];
                if (glo < n) {
                    float2 o;
                    o.x = fmaxf((acc[mf][nf][0] - mu_lo) * rd_lo * g0 + be0, 0.f);
                    o.y = fmaxf((acc[mf][nf][1] - mu_lo) * rd_lo * g1 + be1, 0.f);
                    *(float2*)(g_h1 + (size_t)glo * H + c0) = o;
                }
                if (ghi < n) {
                    float2 o;
                    o.x = fmaxf((acc[mf][nf][2] - mu_hi) * rd_hi * g0 + be0, 0.f);
                    o.y = fmaxf((acc[mf][nf][3] - mu_hi) * rd_hi * g1 + be1, 0.f);
                    *(float2*)(g_h1 + (size_t)ghi * H + c0) = o;
                }
            }
        }
    } else {
        #pragma unroll
        for (int mf = 0; mf < 4; mf++) {
            int lrow = wr * 64 + mf * 16 + lq;
            int glo = row0 + lrow, ghi = glo + 8;
            int klo = 0, khi = 0;
            bool rlo = false, rhi = false;
            if (MODE == 0) {
                klo = kindsh[lrow]; khi = kindsh[lrow + 8];
                rlo = (klo != 0);   rhi = (khi != 0);
            }
            float* dst = (MODE == 0) ? g_h0 : outExt;
            #pragma unroll
            for (int nf = 0; nf < 4; nf++) {
                int c0 = cw * 32 + nf * 8 + 2 * lr;
                if (glo < n) {
                    float2 o = make_float2(acc[mf][nf][0], acc[mf][nf][1]);
                    if (MODE == 0) {
                        o.x += csh[H + klo * H + c0];
                        o.y += csh[H + klo * H + c0 + 1];
                        if (rlo) { o.x += csh[4 * H + c0]; o.y += csh[4 * H + c0 + 1]; }
                    }
                    *(float2*)(dst + (size_t)glo * H + c0) = o;
                }
                if (ghi < n) {
                    float2 o = make_float2(acc[mf][nf][2], acc[mf][nf][3]);
                    if (MODE == 0) {
                        o.x += csh[H + khi * H + c0];
                        o.y += csh[H + khi * H + c0 + 1];
                        if (rhi) { o.x += csh[4 * H + c0]; o.y += csh[4 * H + c0 + 1]; }
                    }
                    *(float2*)(dst + (size_t)ghi * H + c0) = o;
                }
            }
        }
    }
}

// ---------------------------------------------------------------------------
extern "C" void kernel_launch(void* const* d_in, const int* in_sizes, int n_in,
                              void* d_out, int out_size) {
    const float* x          = (const float*)d_in[0];
    const int*   ei         = (const int*)d_in[1];
    const int*   node_kind  = (const int*)d_in[2];
    const float* W_in       = (const float*)d_in[3];
    const float* b_in       = (const float*)d_in[4];
    const float* kind_embed = (const float*)d_in[5];
    const float* ext_seed   = (const float*)d_in[6];
    const float* Wl1        = (const float*)d_in[7];
    const float* bl1        = (const float*)d_in[8];
    const float* Wr1        = (const float*)d_in[9];
    const float* gamma      = (const float*)d_in[10];
    const float* beta       = (const float*)d_in[11];
    const float* Wl2        = (const float*)d_in[12];
    const float* bl2        = (const float*)d_in[13];
    const float* Wr2        = (const float*)d_in[14];

    int n = in_sizes[2];
    int E = in_sizes[1] / 2;

    cudaFuncSetAttribute(tc_gemm<0>, cudaFuncAttributeMaxDynamicSharedMemorySize, SM_BYTES);
    cudaFuncSetAttribute(tc_gemm<1>, cudaFuncAttributeMaxDynamicSharedMemorySize, SM_BYTES);
    cudaFuncSetAttribute(tc_gemm<2>, cudaFuncAttributeMaxDynamicSharedMemorySize, SM_BYTES);

    int ntiles = (n + 127) / 128;
    int nb256  = (n + 255) / 256;
    int eb256  = (E + 255) / 256;
    int aggblk = (n * 32 + 255) / 256;

    // ---- fork: CSR build on side stream, concurrent with prep_w + gemm0 ----
    cudaStream_t s2;
    cudaStreamCreateWithFlags(&s2, cudaStreamNonBlocking);
    cudaEvent_t e1, e2;
    cudaEventCreateWithFlags(&e1, cudaEventDisableTiming);
    cudaEventCreateWithFlags(&e2, cudaEventDisableTiming);

    cudaEventRecord(e1, 0);
    cudaStreamWaitEvent(s2, e1, 0);
    zero_cnt<<<nb256, 256, 0, s2>>>(n);
    hist_kernel<<<eb256, 256, 0, s2>>>(ei, E);
    scan1<<<nb256, 256, 0, s2>>>(n);
    scan2<<<1, 256, 0, s2>>>(nb256);
    scan3<<<nb256, 256, 0, s2>>>(n);
    fill_kernel<<<eb256, 256, 0, s2>>>(ei, E);
    cudaEventRecord(e2, s2);

    // main stream: weight prep then gemm0 (overlaps CSR)
    prep_w<<<(3 * KTOT * H + 255) / 256, 256>>>(W_in, Wl1, Wr1, Wl2, Wr2);
    tc_gemm<0><<<ntiles, TPB, SM_BYTES>>>(x, b_in, kind_embed, ext_seed,
                                          node_kind, nullptr, n);

    // ---- join: aggregate needs both h0 and CSR ----
    cudaStreamWaitEvent(0, e2, 0);
    aggregate_kernel<0><<<aggblk, 256>>>(n);
    tc_gemm<1><<<ntiles, TPB, SM_BYTES>>>(nullptr, bl1, gamma, beta,
                                          nullptr, nullptr, n);
    aggregate_kernel<1><<<aggblk, 256>>>(n);
    tc_gemm<2><<<ntiles, TPB, SM_BYTES>>>(nullptr, bl2, nullptr, nullptr,
                                          nullptr, (float*)d_out, n);
}

// round 16
// speedup vs baseline: 1.1568x; 1.0837x over previous
#include <cuda_runtime.h>
#include <cuda_fp16.h>
#include <cstdint>

#define NMAX 50000
#define EMAX 650000
#define H 128
#define KTOT 256
#define TPB 256
#define WROW 264   // k-pair row stride: 256 + 8 pad

// -------------------- scratch (no allocations allowed) ----------------------
__device__ __half g_h0h[NMAX * H];
__device__ __half g_h1h[NMAX * H];
__device__ float  g_agg[NMAX * H];
__device__ int    g_cnt[NMAX];
__device__ int    g_off[NMAX];
__device__ int    g_cur[NMAX];
__device__ int    g_adj[EMAX];
__device__ int    g_blk[256];
__device__ __align__(16) float g_Wt[3][128 * WROW];  // tf32-rounded smem image

// -------------------- helpers ------------------------------------------------
__device__ __forceinline__ uint32_t tf32r(float x) {
    uint32_t r; asm("cvt.rna.tf32.f32 %0, %1;" : "=r"(r) : "f"(x));
    return r;
}
__device__ __forceinline__ void mma_tf32(float* d, const uint32_t* a, const uint32_t* b) {
    asm volatile("mma.sync.aligned.m16n8k8.row.col.f32.tf32.tf32.f32 "
                 "{%0,%1,%2,%3}, {%4,%5,%6,%7}, {%8,%9}, {%0,%1,%2,%3};"
                 : "+f"(d[0]), "+f"(d[1]), "+f"(d[2]), "+f"(d[3])
                 : "r"(a[0]), "r"(a[1]), "r"(a[2]), "r"(a[3]),
                   "r"(b[0]), "r"(b[1]));
}
__device__ __forceinline__ void cp16(uint32_t dst, const float* src) {
    asm volatile("cp.async.cg.shared.global [%0], [%1], 16;" :: "r"(dst), "l"(src));
}
__device__ __forceinline__ void cp_commit() {
    asm volatile("cp.async.commit_group;" ::: "memory");
}
template<int N>
__device__ __forceinline__ void cp_wait() {
    asm volatile("cp.async.wait_group %0;" :: "n"(N) : "memory");
}

// -------------------- weight prep: tf32-round into smem-image layout ---------
__global__ void prep_w(const float* __restrict__ W_in,
                       const float* __restrict__ Wl1, const float* __restrict__ Wr1,
                       const float* __restrict__ Wl2, const float* __restrict__ Wr2) {
    int i = blockIdx.x * blockDim.x + threadIdx.x;
    if (i >= 3 * KTOT * H) return;
    int col = i & 127;
    int k   = (i >> 7) & 255;
    int m   = i >> 15;
    float v;
    if (m == 0)      v = W_in[k * H + col];
    else if (m == 1) v = (k < H) ? Wl1[k * H + col] : Wr1[(k - H) * H + col];
    else             v = (k < H) ? Wl2[k * H + col] : Wr2[(k - H) * H + col];
    int c  = k >> 5, kk = k & 31;
    int pr = ((kk >> 3) << 2) | (kk & 3);
    int s  = (kk >> 2) & 1;
    g_Wt[m][(c * 16 + pr) * WROW + col * 2 + s] = __uint_as_float(tf32r(v));
}

// -------------------- CSR build ----------------------------------------------
__global__ void zero_cnt(int n) {
    int i = blockIdx.x * blockDim.x + threadIdx.x;
    if (i < n) g_cnt[i] = 0;
}
__global__ void hist_kernel(const int* __restrict__ ei, int E) {
    int e = blockIdx.x * blockDim.x + threadIdx.x;
    if (e < E) atomicAdd(&g_cnt[__ldg(ei + E + e)], 1);
}
__global__ void scan1(int n) {
    __shared__ int smv[256];
    int t = threadIdx.x;
    int i = blockIdx.x * 256 + t;
    int v = (i < n) ? g_cnt[i] : 0;
    smv[t] = v;
    __syncthreads();
    #pragma unroll
    for (int off = 1; off < 256; off <<= 1) {
        int x = (t >= off) ? smv[t - off] : 0;
        __syncthreads();
        smv[t] += x;
        __syncthreads();
    }
    if (i < n) g_off[i] = smv[t] - v;
    if (t == 255) g_blk[blockIdx.x] = smv[255];
}
__global__ void scan2(int nb) {
    __shared__ int smv[256];
    int t = threadIdx.x;
    int v = (t < nb) ? g_blk[t] : 0;
    smv[t] = v;
    __syncthreads();
    #pragma unroll
    for (int off = 1; off < 256; off <<= 1) {
        int x = (t >= off) ? smv[t - off] : 0;
        __syncthreads();
        smv[t] += x;
        __syncthreads();
    }
    if (t < nb) g_blk[t] = smv[t] - v;
}
__global__ void scan3(int n) {
    int i = blockIdx.x * blockDim.x + threadIdx.x;
    if (i < n) {
        int o = g_off[i] + g_blk[i >> 8];
        g_off[i] = o;
        g_cur[i] = o;
    }
}
__global__ void fill_kernel(const int* __restrict__ ei, int E) {
    int e = blockIdx.x * blockDim.x + threadIdx.x;
    if (e < E) {
        int s = __ldg(ei + e);
        int d = __ldg(ei + E + e);
        int p = atomicAdd(&g_cur[d], 1);
        g_adj[p] = s;
    }
}

// -------- CSR aggregate: mean of fp16 h[src] per dst (fp32 accumulate) -------
template<int SRC>
__global__ void aggregate_kernel(int n) {
    int gw = (blockIdx.x * blockDim.x + threadIdx.x) >> 5;
    if (gw >= n) return;
    int lane = threadIdx.x & 31;
    const __half* h = (SRC == 0) ? g_h0h : g_h1h;
    int start = g_off[gw];
    int c = g_cnt[gw];
    float4 acc0 = make_float4(0.f, 0.f, 0.f, 0.f);
    float4 acc1 = make_float4(0.f, 0.f, 0.f, 0.f);
    int j = 0;
    for (; j + 2 <= c; j += 2) {
        int s0 = __ldg(g_adj + start + j);
        int s1 = __ldg(g_adj + start + j + 1);
        float2 r0 = __ldg((const float2*)(h + (size_t)s0 * H) + lane);  // 4 halves
        float2 r1 = __ldg((const float2*)(h + (size_t)s1 * H) + lane);
        __half2* p0 = (__half2*)&r0;
        __half2* p1 = (__half2*)&r1;
        float2 a0 = __half22float2(p0[0]), b0 = __half22float2(p0[1]);
        float2 a1 = __half22float2(p1[0]), b1 = __half22float2(p1[1]);
        acc0.x += a0.x; acc0.y += a0.y; acc0.z += b0.x; acc0.w += b0.y;
        acc1.x += a1.x; acc1.y += a1.y; acc1.z += b1.x; acc1.w += b1.y;
    }
    if (j < c) {
        int s0 = __ldg(g_adj + start + j);
        float2 r0 = __ldg((const float2*)(h + (size_t)s0 * H) + lane);
        __half2* p0 = (__half2*)&r0;
        float2 a0 = __half22float2(p0[0]), b0 = __half22float2(p0[1]);
        acc0.x += a0.x; acc0.y += a0.y; acc0.z += b0.x; acc0.w += b0.y;
    }
    float sc = (c > 0) ? (1.0f / (float)c) : 0.0f;
    float4 o;
    o.x = (acc0.x + acc1.x) * sc;
    o.y = (acc0.y + acc1.y) * sc;
    o.z = (acc0.z + acc1.z) * sc;
    o.w = (acc0.w + acc1.w) * sc;
    ((float4*)(g_agg + (size_t)gw * H))[lane] = o;
}

// smem layout (floats) — same footprint as R15
#define SMF_W     0                       // 3 * 16*264 = 12672 (W ring)
#define SMF_A     12672                   // 2 * 128*32 = 8192
#define SMF_C     20864                   // 768
#define SMF_RS    21632                   // 512
#define SMF_RSS   22144                   // 512
#define SMF_MU    22656                   // 128
#define SMF_RSTD  22784                   // 128
#define SMF_KIND  22912                   // 128
#define SMF_TOTAL 23040
#define SM_BYTES  (SMF_TOTAL * 4)

// ---- pipelined tf32 mma GEMM: 8 warps (64x32 tiles), cp.async W ring, 2 CTA/SM
// MODE 0: A=x[N,256] (fp32), W=Wt0 -> h0h(fp16) = ..+b_in+kind_embed[k]+relay*ext
// MODE 1: A=[agg(fp32) | h0h(fp16)], W=Wt1 -> relu(LN(..+bl1)) -> h1h(fp16)
// MODE 2: A=[agg(fp32) | h1h(fp16)], W=Wt2 -> ..+bl2 -> out(fp32)
template<int MODE>
__global__ void __launch_bounds__(TPB, 2)
tc_gemm(const float* __restrict__ Aext,
        const float* __restrict__ bias,
        const float* __restrict__ aux0,   // MODE0 kind_embed / MODE1 gamma
        const float* __restrict__ aux1,   // MODE0 ext_seed   / MODE1 beta
        const int*   __restrict__ node_kind,
        float* __restrict__ outExt,
        int n)
{
    extern __shared__ float sm[];
    float* Wring[3] = { sm + SMF_W, sm + SMF_W + 16 * WROW, sm + SMF_W + 32 * WROW };
    float* Abuf[2]  = { sm + SMF_A, sm + SMF_A + 128 * 32 };
    float* csh   = sm + SMF_C;
    float* rs    = sm + SMF_RS;
    float* rss   = sm + SMF_RSS;
    float* mus   = sm + SMF_MU;
    float* rstds = sm + SMF_RSTD;
    int*   kindsh = (int*)(sm + SMF_KIND);

    const int tid = threadIdx.x;
    const int wid = tid >> 5;
    const int lid = tid & 31;
    const int lq = lid >> 2;
    const int lr = lid & 3;
    const int wr = wid & 1;        // 2 row-blocks of 64
    const int cw = wid >> 1;       // 4 col-blocks of 32
    const int row0 = blockIdx.x << 7;

    // A staging roles: 2 threads per row, each 16 consecutive k values
    const int arow  = tid >> 1;    // 0..127
    const int khalf = tid & 1;     // 0/1 -> k offset 0/16
    const int agr   = row0 + arow;

    const __half* Hsrc = (MODE == 1) ? g_h0h : g_h1h;
    const float* Wt = g_Wt[MODE];

    uint32_t wsh[3] = { (uint32_t)__cvta_generic_to_shared(Wring[0]),
                        (uint32_t)__cvta_generic_to_shared(Wring[1]),
                        (uint32_t)__cvta_generic_to_shared(Wring[2]) };

    float4 va0, va1, va2, va3;

    auto ldgA = [&](int ch) {
        va0 = make_float4(0.f,0.f,0.f,0.f); va1 = va0; va2 = va0; va3 = va0;
        if (agr < n) {
            if (MODE == 0) {
                const float4* s = (const float4*)(Aext + (size_t)agr * KTOT + ch * 32 + khalf * 16);
                va0 = __ldg(s); va1 = __ldg(s + 1); va2 = __ldg(s + 2); va3 = __ldg(s + 3);
            } else if (ch < 4) {
                const float4* s = (const float4*)(g_agg + (size_t)agr * H + ch * 32 + khalf * 16);
                va0 = __ldg(s); va1 = __ldg(s + 1); va2 = __ldg(s + 2); va3 = __ldg(s + 3);
            } else {
                // fp16 source: 16 halves = 32B = 2 x uint4
                const uint4* s = (const uint4*)(Hsrc + (size_t)agr * H + (ch - 4) * 32 + khalf * 16);
                uint4 r0 = __ldg(s), r1 = __ldg(s + 1);
                __half2* h0p = (__half2*)&r0;
                __half2* h1p = (__half2*)&r1;
                float2 f0 = __half22float2(h0p[0]), f1 = __half22float2(h0p[1]);
                float2 f2 = __half22float2(h0p[2]), f3 = __half22float2(h0p[3]);
                va0 = make_float4(f0.x, f0.y, f1.x, f1.y);
                va1 = make_float4(f2.x, f2.y, f3.x, f3.y);
                f0 = __half22float2(h1p[0]); f1 = __half22float2(h1p[1]);
                f2 = __half22float2(h1p[2]); f3 = __half22float2(h1p[3]);
                va2 = make_float4(f0.x, f0.y, f1.x, f1.y);
                va3 = make_float4(f2.x, f2.y, f3.x, f3.y);
            }
        }
    };
    auto stsA = [&](int p) {
        #pragma unroll
        for (int g = 0; g < 2; g++) {
            float4 xa = g ? va2 : va0;
            float4 xb = g ? va3 : va1;
            int ag = khalf * 2 + g;
            uint4 s0, s1;
            s0.x = tf32r(xa.x); s0.y = tf32r(xb.x);
            s0.z = tf32r(xa.y); s0.w = tf32r(xb.y);
            s1.x = tf32r(xa.z); s1.y = tf32r(xb.z);
            s1.z = tf32r(xa.w); s1.w = tf32r(xb.w);
            int u0 = (ag * 2) ^ ((arow & 3) << 1);
            uint4* d = (uint4*)&Abuf[p][arow * 32 + u0 * 4];
            d[0] = s0; d[1] = s1;
        }
    };
    auto copyW = [&](int ch, int p) {
        const float* src = Wt + ch * 16 * WROW;
        #pragma unroll
        for (int j = 0; j < 5; j++) {
            int f4 = tid + j * TPB;
            if (f4 < 1056) {
                int off = f4 * 4;
                cp16(wsh[p] + off * 4, src + off);
            }
        }
    };

    // ---- prologue ----
    copyW(0, 0); cp_commit();
    copyW(1, 1); cp_commit();
    ldgA(0);
    if (tid < H) csh[tid] = __ldg(bias + tid);
    if (MODE == 0) {
        for (int i = tid; i < 3 * H; i += TPB) csh[H + i] = __ldg(aux0 + i);
        if (tid < H) csh[4 * H + tid] = __ldg(aux1 + tid);
        if (tid < 128) kindsh[tid] = (row0 + tid < n) ? __ldg(node_kind + row0 + tid) : 0;
    } else if (MODE == 1) {
        if (tid < H) { csh[H + tid] = __ldg(aux0 + tid); csh[2 * H + tid] = __ldg(aux1 + tid); }
    }
    stsA(0);
    ldgA(1);
    cp_wait<1>();
    __syncthreads();

    float acc[4][4][4];
    #pragma unroll
    for (int mf = 0; mf < 4; mf++)
        #pragma unroll
        for (int nf = 0; nf < 4; nf++)
            #pragma unroll
            for (int q = 0; q < 4; q++) acc[mf][nf][q] = 0.f;

    int p = 0;
    #pragma unroll
    for (int ch = 0; ch < 8; ch++) {
        if (ch + 2 < 8) { copyW(ch + 2, (ch + 2) % 3); cp_commit(); }

        const float* Ab = Abuf[p];
        const float* Wb = Wring[ch % 3];
        #pragma unroll
        for (int ks = 0; ks < 4; ks++) {
            uint32_t a[4][4];
            #pragma unroll
            for (int mf = 0; mf < 4; mf++) {
                int rlo = wr * 64 + mf * 16 + lq;
                int u = (ks * 2 + (lr >> 1)) ^ ((lq & 3) << 1);
                float2 lo = *(const float2*)&Ab[rlo * 32 + u * 4 + (lr & 1) * 2];
                float2 hi = *(const float2*)&Ab[(rlo + 8) * 32 + u * 4 + (lr & 1) * 2];
                a[mf][0] = __float_as_uint(lo.x);
                a[mf][1] = __float_as_uint(hi.x);
                a[mf][2] = __float_as_uint(lo.y);
                a[mf][3] = __float_as_uint(hi.y);
            }
            uint32_t b[4][2];
            #pragma unroll
            for (int nf = 0; nf < 4; nf++) {
                float2 bv = *(const float2*)&Wb[(ks * 4 + lr) * WROW
                                                + (cw * 32 + nf * 8 + lq) * 2];
                b[nf][0] = __float_as_uint(bv.x);
                b[nf][1] = __float_as_uint(bv.y);
            }
            #pragma unroll
            for (int mf = 0; mf < 4; mf++)
                #pragma unroll
                for (int nf = 0; nf < 4; nf++)
                    mma_tf32(acc[mf][nf], a[mf], b[nf]);
        }
        if (ch < 7) {
            stsA(p ^ 1);
            if (ch < 6) ldgA(ch + 2);
            if (ch + 2 < 8) cp_wait<1>(); else cp_wait<0>();
        }
        __syncthreads();
        p ^= 1;
    }

    // ---------------- epilogue ----------------
    #pragma unroll
    for (int mf = 0; mf < 4; mf++)
        #pragma unroll
        for (int nf = 0; nf < 4; nf++) {
            int c0 = cw * 32 + nf * 8 + 2 * lr;
            float b0v = csh[c0], b1v = csh[c0 + 1];
            acc[mf][nf][0] += b0v; acc[mf][nf][1] += b1v;
            acc[mf][nf][2] += b0v; acc[mf][nf][3] += b1v;
        }

    if (MODE == 1) {
        #pragma unroll
        for (int mf = 0; mf < 4; mf++) {
            float slo = 0.f, sslo = 0.f, shi = 0.f, sshi = 0.f;
            #pragma unroll
            for (int nf = 0; nf < 4; nf++) {
                float v0 = acc[mf][nf][0], v1 = acc[mf][nf][1];
                float v2 = acc[mf][nf][2], v3 = acc[mf][nf][3];
                slo += v0 + v1;  sslo += v0 * v0 + v1 * v1;
                shi += v2 + v3;  sshi += v2 * v2 + v3 * v3;
            }
            #pragma unroll
            for (int m = 1; m <= 2; m <<= 1) {
                slo  += __shfl_xor_sync(0xffffffffu, slo,  m);
                sslo += __shfl_xor_sync(0xffffffffu, sslo, m);
                shi  += __shfl_xor_sync(0xffffffffu, shi,  m);
                sshi += __shfl_xor_sync(0xffffffffu, sshi, m);
            }
            if (lr == 0) {
                int rlo = wr * 64 + mf * 16 + lq;
                rs [rlo * 4 + cw] = slo;       rss[rlo * 4 + cw] = sslo;
                rs [(rlo + 8) * 4 + cw] = shi; rss[(rlo + 8) * 4 + cw] = sshi;
            }
        }
        __syncthreads();
        if (tid < 128) {
            float s  = rs [tid * 4] + rs [tid * 4 + 1] + rs [tid * 4 + 2] + rs [tid * 4 + 3];
            float ss = rss[tid * 4] + rss[tid * 4 + 1] + rss[tid * 4 + 2] + rss[tid * 4 + 3];
            float mu  = s * (1.0f / H);
            float var = ss * (1.0f / H) - mu * mu;
            mus[tid] = mu;
            rstds[tid] = rsqrtf(var + 1e-5f);
        }
        __syncthreads();
        #pragma unroll
        for (int mf = 0; mf < 4; mf++) {
            int lrow = wr * 64 + mf * 16 + lq;
            float mu_lo = mus[lrow],     rd_lo = rstds[lrow];
            float mu_hi = mus[lrow + 8], rd_hi = rstds[lrow + 8];
            int glo = row0 + lrow, ghi = glo + 8;
            #pragma unroll
            for (int nf = 0; nf < 4; nf++) {
                int c0 = cw * 32 + nf * 8 + 2 * lr;
                float g0 = csh[H + c0], g1 = csh[H + c0 + 1];
                float be0 = csh[2 * H + c0], be1 = csh[2 * H + c0 + 1];
                if (glo < n) {
                    float ox = fmaxf((acc[mf][nf][0] - mu_lo) * rd_lo * g0 + be0, 0.f);
                    float oy = fmaxf((acc[mf][nf][1] - mu_lo) * rd_lo * g1 + be1, 0.f);
                    *(__half2*)(g_h1h + (size_t)glo * H + c0) = __floats2half2_rn(ox, oy);
                }
                if (ghi < n) {
                    float ox = fmaxf((acc[mf][nf][2] - mu_hi) * rd_hi * g0 + be0, 0.f);
                    float oy = fmaxf((acc[mf][nf][3] - mu_hi) * rd_hi * g1 + be1, 0.f);
                    *(__half2*)(g_h1h + (size_t)ghi * H + c0) = __floats2half2_rn(ox, oy);
                }
            }
        }
    } else {
        #pragma unroll
        for (int mf = 0; mf < 4; mf++) {
            int lrow = wr * 64 + mf * 16 + lq;
            int glo = row0 + lrow, ghi = glo + 8;
            int klo = 0, khi = 0;
            bool rlo = false, rhi = false;
            if (MODE == 0) {
                klo = kindsh[lrow]; khi = kindsh[lrow + 8];
                rlo = (klo != 0);   rhi = (khi != 0);
            }
            #pragma unroll
            for (int nf = 0; nf < 4; nf++) {
                int c0 = cw * 32 + nf * 8 + 2 * lr;
                if (glo < n) {
                    float ox = acc[mf][nf][0], oy = acc[mf][nf][1];
                    if (MODE == 0) {
                        ox += csh[H + klo * H + c0];
                        oy += csh[H + klo * H + c0 + 1];
                        if (rlo) { ox += csh[4 * H + c0]; oy += csh[4 * H + c0 + 1]; }
                        *(__half2*)(g_h0h + (size_t)glo * H + c0) = __floats2half2_rn(ox, oy);
                    } else {
                        *(float2*)(outExt + (size_t)glo * H + c0) = make_float2(ox, oy);
                    }
                }
                if (ghi < n) {
                    float ox = acc[mf][nf][2], oy = acc[mf][nf][3];
                    if (MODE == 0) {
                        ox += csh[H + khi * H + c0];
                        oy += csh[H + khi * H + c0 + 1];
                        if (rhi) { ox += csh[4 * H + c0]; oy += csh[4 * H + c0 + 1]; }
                        *(__half2*)(g_h0h + (size_t)ghi * H + c0) = __floats2half2_rn(ox, oy);
                    } else {
                        *(float2*)(outExt + (size_t)ghi * H + c0) = make_float2(ox, oy);
                    }
                }
            }
        }
    }
}

// ---------------------------------------------------------------------------
extern "C" void kernel_launch(void* const* d_in, const int* in_sizes, int n_in,
                              void* d_out, int out_size) {
    const float* x          = (const float*)d_in[0];
    const int*   ei         = (const int*)d_in[1];
    const int*   node_kind  = (const int*)d_in[2];
    const float* W_in       = (const float*)d_in[3];
    const float* b_in       = (const float*)d_in[4];
    const float* kind_embed = (const float*)d_in[5];
    const float* ext_seed   = (const float*)d_in[6];
    const float* Wl1        = (const float*)d_in[7];
    const float* bl1        = (const float*)d_in[8];
    const float* Wr1        = (const float*)d_in[9];
    const float* gamma      = (const float*)d_in[10];
    const float* beta       = (const float*)d_in[11];
    const float* Wl2        = (const float*)d_in[12];
    const float* bl2        = (const float*)d_in[13];
    const float* Wr2        = (const float*)d_in[14];

    int n = in_sizes[2];
    int E = in_sizes[1] / 2;

    cudaFuncSetAttribute(tc_gemm<0>, cudaFuncAttributeMaxDynamicSharedMemorySize, SM_BYTES);
    cudaFuncSetAttribute(tc_gemm<1>, cudaFuncAttributeMaxDynamicSharedMemorySize, SM_BYTES);
    cudaFuncSetAttribute(tc_gemm<2>, cudaFuncAttributeMaxDynamicSharedMemorySize, SM_BYTES);

    int ntiles = (n + 127) / 128;
    int nb256  = (n + 255) / 256;
    int eb256  = (E + 255) / 256;
    int aggblk = (n * 32 + 255) / 256;

    // ---- fork: CSR build on side stream, concurrent with prep_w + gemm0 ----
    cudaStream_t s2;
    cudaStreamCreateWithFlags(&s2, cudaStreamNonBlocking);
    cudaEvent_t e1, e2;
    cudaEventCreateWithFlags(&e1, cudaEventDisableTiming);
    cudaEventCreateWithFlags(&e2, cudaEventDisableTiming);

    cudaEventRecord(e1, 0);
    cudaStreamWaitEvent(s2, e1, 0);
    zero_cnt<<<nb256, 256, 0, s2>>>(n);
    hist_kernel<<<eb256, 256, 0, s2>>>(ei, E);
    scan1<<<nb256, 256, 0, s2>>>(n);
    scan2<<<1, 256, 0, s2>>>(nb256);
    scan3<<<nb256, 256, 0, s2>>>(n);
    fill_kernel<<<eb256, 256, 0, s2>>>(ei, E);
    cudaEventRecord(e2, s2);

    // main stream: weight prep then gemm0 (overlaps CSR)
    prep_w<<<(3 * KTOT * H + 255) / 256, 256>>>(W_in, Wl1, Wr1, Wl2, Wr2);
    tc_gemm<0><<<ntiles, TPB, SM_BYTES>>>(x, b_in, kind_embed, ext_seed,
                                          node_kind, nullptr, n);

    // ---- join: aggregate needs both h0 and CSR ----
    cudaStreamWaitEvent(0, e2, 0);
    aggregate_kernel<0><<<aggblk, 256>>>(n);
    tc_gemm<1><<<ntiles, TPB, SM_BYTES>>>(nullptr, bl1, gamma, beta,
                                          nullptr, nullptr, n);
    aggregate_kernel<1><<<aggblk, 256>>>(n);
    tc_gemm<2><<<ntiles, TPB, SM_BYTES>>>(nullptr, bl2, nullptr, nullptr,
                                          nullptr, (float*)d_out, n);
}

// round 17
// speedup vs baseline: 1.2673x; 1.0955x over previous
#include <cuda_runtime.h>
#include <cuda_fp16.h>
#include <cstdint>

#define NMAX 50000
#define EMAX 650000
#define H 128
#define KTOT 256
#define TPB 256
#define WPL 528        // halves per plane: 128*4 + 16 pad (1056 B, ≡8 words mod 32)
#define PLB 1056       // plane bytes

// -------------------- scratch (no allocations allowed) ----------------------
__device__ __half g_h0h[NMAX * H];
__device__ __half g_h1h[NMAX * H];
__device__ float  g_agg[NMAX * H];
__device__ int    g_cnt[NMAX];
__device__ int    g_off[NMAX];
__device__ int    g_cur[NMAX];
__device__ int    g_adj[EMAX];
__device__ int    g_blk[256];
__device__ __align__(16) __half g_Wth[3][64 * WPL];  // fp16 plane-major W images

// -------------------- helpers ------------------------------------------------
__device__ __forceinline__ uint32_t f2h2(float a, float b) {
    __half2 h = __floats2half2_rn(a, b);
    return *(uint32_t*)&h;
}
__device__ __forceinline__ void mma_f16(float* d, const uint32_t* a, const uint32_t* b) {
    asm volatile("mma.sync.aligned.m16n8k16.row.col.f32.f16.f16.f32 "
                 "{%0,%1,%2,%3}, {%4,%5,%6,%7}, {%8,%9}, {%0,%1,%2,%3};"
                 : "+f"(d[0]), "+f"(d[1]), "+f"(d[2]), "+f"(d[3])
                 : "r"(a[0]), "r"(a[1]), "r"(a[2]), "r"(a[3]),
                   "r"(b[0]), "r"(b[1]));
}
__device__ __forceinline__ void cp16(uint32_t dst, const void* src) {
    asm volatile("cp.async.cg.shared.global [%0], [%1], 16;" :: "r"(dst), "l"(src));
}
__device__ __forceinline__ void cp_commit() {
    asm volatile("cp.async.commit_group;" ::: "memory");
}
template<int N>
__device__ __forceinline__ void cp_wait() {
    asm volatile("cp.async.wait_group %0;" :: "n"(N) : "memory");
}

// ---- weight prep: fp16-round into plane-major image -------------------------
// plane = (k>>4)*4 + g, where within the k16 block: k'<8 -> g=k'>>1, pos=k'&1;
// k'>=8 -> g=(k'-8)>>1, pos=2+(k'&1). slot = col*4 + pos.
__global__ void prep_w(const float* __restrict__ W_in,
                       const float* __restrict__ Wl1, const float* __restrict__ Wr1,
                       const float* __restrict__ Wl2, const float* __restrict__ Wr2) {
    int i = blockIdx.x * blockDim.x + threadIdx.x;
    if (i >= 3 * KTOT * H) return;
    int col = i & 127;
    int k   = (i >> 7) & 255;
    int m   = i >> 15;
    float v;
    if (m == 0)      v = W_in[k * H + col];
    else if (m == 1) v = (k < H) ? Wl1[k * H + col] : Wr1[(k - H) * H + col];
    else             v = (k < H) ? Wl2[k * H + col] : Wr2[(k - H) * H + col];
    int blk = k >> 4, kk = k & 15;
    int g, pos;
    if (kk < 8) { g = kk >> 1; pos = kk & 1; }
    else        { g = (kk - 8) >> 1; pos = 2 + (kk & 1); }
    g_Wth[m][(blk * 4 + g) * WPL + col * 4 + pos] = __float2half_rn(v);
}

// -------------------- CSR build ----------------------------------------------
__global__ void zero_cnt(int n) {
    int i = blockIdx.x * blockDim.x + threadIdx.x;
    if (i < n) g_cnt[i] = 0;
}
__global__ void hist_kernel(const int* __restrict__ ei, int E) {
    int e = blockIdx.x * blockDim.x + threadIdx.x;
    if (e < E) atomicAdd(&g_cnt[__ldg(ei + E + e)], 1);
}
__global__ void scan1(int n) {
    __shared__ int smv[256];
    int t = threadIdx.x;
    int i = blockIdx.x * 256 + t;
    int v = (i < n) ? g_cnt[i] : 0;
    smv[t] = v;
    __syncthreads();
    #pragma unroll
    for (int off = 1; off < 256; off <<= 1) {
        int x = (t >= off) ? smv[t - off] : 0;
        __syncthreads();
        smv[t] += x;
        __syncthreads();
    }
    if (i < n) g_off[i] = smv[t] - v;
    if (t == 255) g_blk[blockIdx.x] = smv[255];
}
__global__ void scan2(int nb) {
    __shared__ int smv[256];
    int t = threadIdx.x;
    int v = (t < nb) ? g_blk[t] : 0;
    smv[t] = v;
    __syncthreads();
    #pragma unroll
    for (int off = 1; off < 256; off <<= 1) {
        int x = (t >= off) ? smv[t - off] : 0;
        __syncthreads();
        smv[t] += x;
        __syncthreads();
    }
    if (t < nb) g_blk[t] = smv[t] - v;
}
__global__ void scan3(int n) {
    int i = blockIdx.x * blockDim.x + threadIdx.x;
    if (i < n) {
        int o = g_off[i] + g_blk[i >> 8];
        g_off[i] = o;
        g_cur[i] = o;
    }
}
__global__ void fill_kernel(const int* __restrict__ ei, int E) {
    int e = blockIdx.x * blockDim.x + threadIdx.x;
    if (e < E) {
        int s = __ldg(ei + e);
        int d = __ldg(ei + E + e);
        int p = atomicAdd(&g_cur[d], 1);
        g_adj[p] = s;
    }
}

// -------- CSR aggregate: mean of fp16 h[src] per dst (fp32 accumulate) -------
template<int SRC>
__global__ void aggregate_kernel(int n) {
    int gw = (blockIdx.x * blockDim.x + threadIdx.x) >> 5;
    if (gw >= n) return;
    int lane = threadIdx.x & 31;
    const __half* h = (SRC == 0) ? g_h0h : g_h1h;
    int start = g_off[gw];
    int c = g_cnt[gw];
    float4 acc0 = make_float4(0.f, 0.f, 0.f, 0.f);
    float4 acc1 = make_float4(0.f, 0.f, 0.f, 0.f);
    int j = 0;
    for (; j + 2 <= c; j += 2) {
        int s0 = __ldg(g_adj + start + j);
        int s1 = __ldg(g_adj + start + j + 1);
        float2 r0 = __ldg((const float2*)(h + (size_t)s0 * H) + lane);
        float2 r1 = __ldg((const float2*)(h + (size_t)s1 * H) + lane);
        __half2* p0 = (__half2*)&r0;
        __half2* p1 = (__half2*)&r1;
        float2 a0 = __half22float2(p0[0]), b0 = __half22float2(p0[1]);
        float2 a1 = __half22float2(p1[0]), b1 = __half22float2(p1[1]);
        acc0.x += a0.x; acc0.y += a0.y; acc0.z += b0.x; acc0.w += b0.y;
        acc1.x += a1.x; acc1.y += a1.y; acc1.z += b1.x; acc1.w += b1.y;
    }
    if (j < c) {
        int s0 = __ldg(g_adj + start + j);
        float2 r0 = __ldg((const float2*)(h + (size_t)s0 * H) + lane);
        __half2* p0 = (__half2*)&r0;
        float2 a0 = __half22float2(p0[0]), b0 = __half22float2(p0[1]);
        acc0.x += a0.x; acc0.y += a0.y; acc0.z += b0.x; acc0.w += b0.y;
    }
    float sc = (c > 0) ? (1.0f / (float)c) : 0.0f;
    float4 o;
    o.x = (acc0.x + acc1.x) * sc;
    o.y = (acc0.y + acc1.y) * sc;
    o.z = (acc0.z + acc1.z) * sc;
    o.w = (acc0.w + acc1.w) * sc;
    ((float4*)(g_agg + (size_t)gw * H))[lane] = o;
}

// smem layout (bytes)
#define SMB_W     0                       // 3 chunks * 8 planes * 1056 = 25344
#define SMB_A     25344                   // 2 bufs  * 8 planes * 1056 = 16896
#define SMB_C     42240                   // csh 768 floats = 3072
#define SMB_RS    45312                   // 2048
#define SMB_RSS   47360                   // 2048
#define SMB_MU    49408                   // 512
#define SMB_RSTD  49920                   // 512
#define SMB_KIND  50432                   // 512
#define SM_BYTES  50944

// ---- fp16 m16n8k16 GEMM: 8 warps (64x32 tiles), cp.async W ring, 2 CTA/SM ----
// MODE 0: A=x[N,256] fp32 -> fp16, W=Wt0 -> h0h = ..+b_in+kind_embed+relay*ext
// MODE 1: A=[agg fp32 | h0h fp16], W=Wt1 -> relu(LN(..+bl1)) -> h1h
// MODE 2: A=[agg fp32 | h1h fp16], W=Wt2 -> ..+bl2 -> out fp32
template<int MODE>
__global__ void __launch_bounds__(TPB, 2)
tc_gemm(const float* __restrict__ Aext,
        const float* __restrict__ bias,
        const float* __restrict__ aux0,   // MODE0 kind_embed / MODE1 gamma
        const float* __restrict__ aux1,   // MODE0 ext_seed   / MODE1 beta
        const int*   __restrict__ node_kind,
        float* __restrict__ outExt,
        int n)
{
    extern __shared__ char smc[];
    __half* Wring[3] = { (__half*)(smc + SMB_W),
                         (__half*)(smc + SMB_W + 8 * PLB),
                         (__half*)(smc + SMB_W + 16 * PLB) };
    __half* Abuf[2]  = { (__half*)(smc + SMB_A),
                         (__half*)(smc + SMB_A + 8 * PLB) };
    float* csh   = (float*)(smc + SMB_C);
    float* rs    = (float*)(smc + SMB_RS);
    float* rss   = (float*)(smc + SMB_RSS);
    float* mus   = (float*)(smc + SMB_MU);
    float* rstds = (float*)(smc + SMB_RSTD);
    int*   kindsh = (int*)(smc + SMB_KIND);

    const int tid = threadIdx.x;
    const int wid = tid >> 5;
    const int lid = tid & 31;
    const int lq = lid >> 2;
    const int lr = lid & 3;
    const int wr = wid & 1;        // 2 row-blocks of 64
    const int cw = wid >> 1;       // 4 col-blocks of 32
    const int row0 = blockIdx.x << 7;

    // staging roles: first 128 threads = k-half 0, second 128 = k-half 1
    const int arow = tid & 127;
    const int kh   = tid >> 7;     // 0/1 -> k offset 0/16 within chunk
    const int agr  = row0 + arow;

    const __half* Hsrc = (MODE == 1) ? g_h0h : g_h1h;
    const __half* Wt = g_Wth[MODE];

    uint32_t wsh[3] = { (uint32_t)__cvta_generic_to_shared(Wring[0]),
                        (uint32_t)__cvta_generic_to_shared(Wring[1]),
                        (uint32_t)__cvta_generic_to_shared(Wring[2]) };

    // 16 staged halves per thread as 8 packed pairs:
    // plo[g] = halves (2g, 2g+1) ; phi[g] = halves (2g+8, 2g+9)
    uint32_t plo[4], phi[4];

    auto ldgA = [&](int ch) {
        #pragma unroll
        for (int g = 0; g < 4; g++) { plo[g] = 0; phi[g] = 0; }
        if (agr < n) {
            if (MODE == 0 || ch < 4) {
                const float4* s;
                if (MODE == 0)
                    s = (const float4*)(Aext + (size_t)agr * KTOT + ch * 32 + kh * 16);
                else
                    s = (const float4*)(g_agg + (size_t)agr * H + ch * 32 + kh * 16);
                float4 v0 = __ldg(s), v1 = __ldg(s + 1), v2 = __ldg(s + 2), v3 = __ldg(s + 3);
                plo[0] = f2h2(v0.x, v0.y); plo[1] = f2h2(v0.z, v0.w);
                plo[2] = f2h2(v1.x, v1.y); plo[3] = f2h2(v1.z, v1.w);
                phi[0] = f2h2(v2.x, v2.y); phi[1] = f2h2(v2.z, v2.w);
                phi[2] = f2h2(v3.x, v3.y); phi[3] = f2h2(v3.z, v3.w);
            } else {
                const uint4* s = (const uint4*)(Hsrc + (size_t)agr * H + (ch - 4) * 32 + kh * 16);
                uint4 r0 = __ldg(s), r1 = __ldg(s + 1);
                plo[0] = r0.x; plo[1] = r0.y; plo[2] = r0.z; plo[3] = r0.w;
                phi[0] = r1.x; phi[1] = r1.y; phi[2] = r1.z; phi[3] = r1.w;
            }
        }
    };
    auto stsA = [&](int p) {
        #pragma unroll
        for (int g = 0; g < 4; g++)
            *(uint2*)(Abuf[p] + (kh * 4 + g) * WPL + arow * 4) = make_uint2(plo[g], phi[g]);
    };
    auto copyW = [&](int ch, int p) {
        const __half* src = Wt + ch * 8 * WPL;
        #pragma unroll
        for (int j = 0; j < 3; j++) {
            int f4 = tid + j * TPB;
            if (f4 < 528) cp16(wsh[p] + f4 * 16, (const char*)src + f4 * 16);
        }
    };

    // ---- prologue ----
    copyW(0, 0); cp_commit();
    copyW(1, 1); cp_commit();
    ldgA(0);
    if (tid < H) csh[tid] = __ldg(bias + tid);
    if (MODE == 0) {
        for (int i = tid; i < 3 * H; i += TPB) csh[H + i] = __ldg(aux0 + i);
        if (tid < H) csh[4 * H + tid] = __ldg(aux1 + tid);
        if (tid < 128) kindsh[tid] = (row0 + tid < n) ? __ldg(node_kind + row0 + tid) : 0;
    } else if (MODE == 1) {
        if (tid < H) { csh[H + tid] = __ldg(aux0 + tid); csh[2 * H + tid] = __ldg(aux1 + tid); }
    }
    stsA(0);
    ldgA(1);
    cp_wait<1>();
    __syncthreads();

    float acc[4][4][4];
    #pragma unroll
    for (int mf = 0; mf < 4; mf++)
        #pragma unroll
        for (int nf = 0; nf < 4; nf++)
            #pragma unroll
            for (int q = 0; q < 4; q++) acc[mf][nf][q] = 0.f;

    int p = 0;
    #pragma unroll
    for (int ch = 0; ch < 8; ch++) {
        if (ch + 2 < 8) { copyW(ch + 2, (ch + 2) % 3); cp_commit(); }

        const __half* Ab = Abuf[p];
        const __half* Wb = Wring[ch % 3];
        #pragma unroll
        for (int b2 = 0; b2 < 2; b2++) {
            uint32_t a[4][4];
            #pragma unroll
            for (int mf = 0; mf < 4; mf++) {
                int r = wr * 64 + mf * 16 + lq;
                uint2 lo = *(const uint2*)(Ab + (b2 * 4 + lr) * WPL + r * 4);
                uint2 hi = *(const uint2*)(Ab + (b2 * 4 + lr) * WPL + (r + 8) * 4);
                a[mf][0] = lo.x; a[mf][1] = hi.x; a[mf][2] = lo.y; a[mf][3] = hi.y;
            }
            uint32_t b[4][2];
            #pragma unroll
            for (int nf = 0; nf < 4; nf++) {
                int nn = cw * 32 + nf * 8 + lq;
                uint2 bv = *(const uint2*)(Wb + (b2 * 4 + lr) * WPL + nn * 4);
                b[nf][0] = bv.x; b[nf][1] = bv.y;
            }
            #pragma unroll
            for (int mf = 0; mf < 4; mf++)
                #pragma unroll
                for (int nf = 0; nf < 4; nf++)
                    mma_f16(acc[mf][nf], a[mf], b[nf]);
        }
        if (ch < 7) {
            stsA(p ^ 1);
            if (ch < 6) ldgA(ch + 2);
            if (ch + 2 < 8) cp_wait<1>(); else cp_wait<0>();
        }
        __syncthreads();
        p ^= 1;
    }

    // ---------------- epilogue (same accumulator/column mapping as R16) ------
    #pragma unroll
    for (int mf = 0; mf < 4; mf++)
        #pragma unroll
        for (int nf = 0; nf < 4; nf++) {
            int c0 = cw * 32 + nf * 8 + 2 * lr;
            float b0v = csh[c0], b1v = csh[c0 + 1];
            acc[mf][nf][0] += b0v; acc[mf][nf][1] += b1v;
            acc[mf][nf][2] += b0v; acc[mf][nf][3] += b1v;
        }

    if (MODE == 1) {
        #pragma unroll
        for (int mf = 0; mf < 4; mf++) {
            float slo = 0.f, sslo = 0.f, shi = 0.f, sshi = 0.f;
            #pragma unroll
            for (int nf = 0; nf < 4; nf++) {
                float v0 = acc[mf][nf][0], v1 = acc[mf][nf][1];
                float v2 = acc[mf][nf][2], v3 = acc[mf][nf][3];
                slo += v0 + v1;  sslo += v0 * v0 + v1 * v1;
                shi += v2 + v3;  sshi += v2 * v2 + v3 * v3;
            }
            #pragma unroll
            for (int m = 1; m <= 2; m <<= 1) {
                slo  += __shfl_xor_sync(0xffffffffu, slo,  m);
                sslo += __shfl_xor_sync(0xffffffffu, sslo, m);
                shi  += __shfl_xor_sync(0xffffffffu, shi,  m);
                sshi += __shfl_xor_sync(0xffffffffu, sshi, m);
            }
            if (lr == 0) {
                int rlo = wr * 64 + mf * 16 + lq;
                rs [rlo * 4 + cw] = slo;       rss[rlo * 4 + cw] = sslo;
                rs [(rlo + 8) * 4 + cw] = shi; rss[(rlo + 8) * 4 + cw] = sshi;
            }
        }
        __syncthreads();
        if (tid < 128) {
            float s  = rs [tid * 4] + rs [tid * 4 + 1] + rs [tid * 4 + 2] + rs [tid * 4 + 3];
            float ss = rss[tid * 4] + rss[tid * 4 + 1] + rss[tid * 4 + 2] + rss[tid * 4 + 3];
            float mu  = s * (1.0f / H);
            float var = ss * (1.0f / H) - mu * mu;
            mus[tid] = mu;
            rstds[tid] = rsqrtf(var + 1e-5f);
        }
        __syncthreads();
        #pragma unroll
        for (int mf = 0; mf < 4; mf++) {
            int lrow = wr * 64 + mf * 16 + lq;
            float mu_lo = mus[lrow],     rd_lo = rstds[lrow];
            float mu_hi = mus[lrow + 8], rd_hi = rstds[lrow + 8];
            int glo = row0 + lrow, ghi = glo + 8;
            #pragma unroll
            for (int nf = 0; nf < 4; nf++) {
                int c0 = cw * 32 + nf * 8 + 2 * lr;
                float g0 = csh[H + c0], g1 = csh[H + c0 + 1];
                float be0 = csh[2 * H + c0], be1 = csh[2 * H + c0 + 1];
                if (glo < n) {
                    float ox = fmaxf((acc[mf][nf][0] - mu_lo) * rd_lo * g0 + be0, 0.f);
                    float oy = fmaxf((acc[mf][nf][1] - mu_lo) * rd_lo * g1 + be1, 0.f);
                    *(__half2*)(g_h1h + (size_t)glo * H + c0) = __floats2half2_rn(ox, oy);
                }
                if (ghi < n) {
                    float ox = fmaxf((acc[mf][nf][2] - mu_hi) * rd_hi * g0 + be0, 0.f);
                    float oy = fmaxf((acc[mf][nf][3] - mu_hi) * rd_hi * g1 + be1, 0.f);
                    *(__half2*)(g_h1h + (size_t)ghi * H + c0) = __floats2half2_rn(ox, oy);
                }
            }
        }
    } else {
        #pragma unroll
        for (int mf = 0; mf < 4; mf++) {
            int lrow = wr * 64 + mf * 16 + lq;
            int glo = row0 + lrow, ghi = glo + 8;
            int klo = 0, khi = 0;
            bool rlo = false, rhi = false;
            if (MODE == 0) {
                klo = kindsh[lrow]; khi = kindsh[lrow + 8];
                rlo = (klo != 0);   rhi = (khi != 0);
            }
            #pragma unroll
            for (int nf = 0; nf < 4; nf++) {
                int c0 = cw * 32 + nf * 8 + 2 * lr;
                if (glo < n) {
                    float ox = acc[mf][nf][0], oy = acc[mf][nf][1];
                    if (MODE == 0) {
                        ox += csh[H + klo * H + c0];
                        oy += csh[H + klo * H + c0 + 1];
                        if (rlo) { ox += csh[4 * H + c0]; oy += csh[4 * H + c0 + 1]; }
                        *(__half2*)(g_h0h + (size_t)glo * H + c0) = __floats2half2_rn(ox, oy);
                    } else {
                        *(float2*)(outExt + (size_t)glo * H + c0) = make_float2(ox, oy);
                    }
                }
                if (ghi < n) {
                    float ox = acc[mf][nf][2], oy = acc[mf][nf][3];
                    if (MODE == 0) {
                        ox += csh[H + khi * H + c0];
                        oy += csh[H + khi * H + c0 + 1];
                        if (rhi) { ox += csh[4 * H + c0]; oy += csh[4 * H + c0 + 1]; }
                        *(__half2*)(g_h0h + (size_t)ghi * H + c0) = __floats2half2_rn(ox, oy);
                    } else {
                        *(float2*)(outExt + (size_t)ghi * H + c0) = make_float2(ox, oy);
                    }
                }
            }
        }
    }
}

// ---------------------------------------------------------------------------
extern "C" void kernel_launch(void* const* d_in, const int* in_sizes, int n_in,
                              void* d_out, int out_size) {
    const float* x          = (const float*)d_in[0];
    const int*   ei         = (const int*)d_in[1];
    const int*   node_kind  = (const int*)d_in[2];
    const float* W_in       = (const float*)d_in[3];
    const float* b_in       = (const float*)d_in[4];
    const float* kind_embed = (const float*)d_in[5];
    const float* ext_seed   = (const float*)d_in[6];
    const float* Wl1        = (const float*)d_in[7];
    const float* bl1        = (const float*)d_in[8];
    const float* Wr1        = (const float*)d_in[9];
    const float* gamma      = (const float*)d_in[10];
    const float* beta       = (const float*)d_in[11];
    const float* Wl2        = (const float*)d_in[12];
    const float* bl2        = (const float*)d_in[13];
    const float* Wr2        = (const float*)d_in[14];

    int n = in_sizes[2];
    int E = in_sizes[1] / 2;

    cudaFuncSetAttribute(tc_gemm<0>, cudaFuncAttributeMaxDynamicSharedMemorySize, SM_BYTES);
    cudaFuncSetAttribute(tc_gemm<1>, cudaFuncAttributeMaxDynamicSharedMemorySize, SM_BYTES);
    cudaFuncSetAttribute(tc_gemm<2>, cudaFuncAttributeMaxDynamicSharedMemorySize, SM_BYTES);

    int ntiles = (n + 127) / 128;
    int nb256  = (n + 255) / 256;
    int eb256  = (E + 255) / 256;
    int aggblk = (n * 32 + 255) / 256;

    // ---- fork: CSR build on side stream, concurrent with prep_w + gemm0 ----
    cudaStream_t s2;
    cudaStreamCreateWithFlags(&s2, cudaStreamNonBlocking);
    cudaEvent_t e1, e2;
    cudaEventCreateWithFlags(&e1, cudaEventDisableTiming);
    cudaEventCreateWithFlags(&e2, cudaEventDisableTiming);

    cudaEventRecord(e1, 0);
    cudaStreamWaitEvent(s2, e1, 0);
    zero_cnt<<<nb256, 256, 0, s2>>>(n);
    hist_kernel<<<eb256, 256, 0, s2>>>(ei, E);
    scan1<<<nb256, 256, 0, s2>>>(n);
    scan2<<<1, 256, 0, s2>>>(nb256);
    scan3<<<nb256, 256, 0, s2>>>(n);
    fill_kernel<<<eb256, 256, 0, s2>>>(ei, E);
    cudaEventRecord(e2, s2);

    // main stream: weight prep then gemm0 (overlaps CSR)
    prep_w<<<(3 * KTOT * H + 255) / 256, 256>>>(W_in, Wl1, Wr1, Wl2, Wr2);
    tc_gemm<0><<<ntiles, TPB, SM_BYTES>>>(x, b_in, kind_embed, ext_seed,
                                          node_kind, nullptr, n);

    // ---- join: aggregate needs both h0 and CSR ----
    cudaStreamWaitEvent(0, e2, 0);
    aggregate_kernel<0><<<aggblk, 256>>>(n);
    tc_gemm<1><<<ntiles, TPB, SM_BYTES>>>(nullptr, bl1, gamma, beta,
                                          nullptr, nullptr, n);
    aggregate_kernel<1><<<aggblk, 256>>>(n);
    tc_gemm<2><<<ntiles, TPB, SM_BYTES>>>(nullptr, bl2, nullptr, nullptr,
                                          nullptr, (float*)d_out, n);
}